// round 16
// baseline (speedup 1.0000x reference)
#include <cuda_runtime.h>
#include <math.h>

#define BATCH 2048
#define NQ    10
#define NGEN  4
#define DEPTH 6
#define PATCH 256
#define QOUT  1024
#define NCLS  10

typedef unsigned long long u64;

// ---------------- scratch (device globals; no allocation) ----------------
__device__ __align__(256) float g_angles[BATCH * 2 * NQ];   // (B,20)
__device__ __align__(256) float g_qf[BATCH * QOUT];         // (B,1024)
__device__ __align__(256) float g_y1[BATCH * 128];
__device__ __align__(256) float g_y2[BATCH * 128];
__device__ __align__(16)  float g_wc[NGEN * DEPTH * NQ];    // cos(th/2)
__device__ __align__(16)  float g_ws[NGEN * DEPTH * NQ];    // sin(th/2)
__device__ __align__(16)  float g_wt[NGEN * DEPTH * NQ];    // tan(th/4)
__device__ __align__(256) float g_ps1[128][128], g_pq1[128][128]; // BN1 partials
__device__ __align__(256) float g_ps2[64][128],  g_pq2[64][128];  // BN2 partials
__device__ __align__(256) float g_p1[4][BATCH * 128];  // gemm1 split-K partials
__device__ __align__(256) float g_wtail[NCLS][128];    // pw1 label-tail, transposed

__device__ __forceinline__ float leaky(float x) { return x > 0.f ? x : 0.2f * x; }

// ---------------- packed f32x2 helpers ----------------
__device__ __forceinline__ u64 pk2(float lo, float hi) {
    u64 r; asm("mov.b64 %0,{%1,%2};" : "=l"(r) : "f"(lo), "f"(hi)); return r;
}
__device__ __forceinline__ void upk2(float& lo, float& hi, u64 v) {
    asm("mov.b64 {%0,%1},%2;" : "=f"(lo), "=f"(hi) : "l"(v));
}
__device__ __forceinline__ u64 f2fma(u64 a, u64 b, u64 c) {
    u64 d; asm("fma.rn.f32x2 %0,%1,%2,%3;" : "=l"(d) : "l"(a), "l"(b), "l"(c)); return d;
}
__device__ __forceinline__ u64 f2mul(u64 a, u64 b) {
    u64 d; asm("mul.rn.f32x2 %0,%1,%2;" : "=l"(d) : "l"(a), "l"(b)); return d;
}
__device__ __forceinline__ float2 cmul(float2 a, float2 b) {
    return make_float2(fmaf(a.x, b.x, -a.y * b.y), fmaf(a.x, b.y, a.y * b.x));
}

// =====================================================================
// Launch 1: embedding MLP (blocks 0..255) + table precompute (block 256)
// =====================================================================
__global__ void __launch_bounds__(256) embed_kernel(
    const float* __restrict__ lab, const float* __restrict__ qp,
    const float* __restrict__ pw1,
    const float* __restrict__ ew1, const float* __restrict__ eb1,
    const float* __restrict__ ew2, const float* __restrict__ eb2,
    const float* __restrict__ ew3, const float* __restrict__ eb3)
{
    if (blockIdx.x == 256) {
        const int i = threadIdx.x;
        if (i < NGEN * DEPTH * NQ) {
            float s, c; __sincosf(0.5f * qp[i], &s, &c);
            g_wc[i] = c; g_ws[i] = s;
            g_wt[i] = __fdividef(s, 1.f + c);      // tan(th/4), th in [0,1)
        }
        if (i < 128) {
#pragma unroll
            for (int c = 0; c < NCLS; ++c)
                g_wtail[c][i] = pw1[i * 1034 + QOUT + c];
        }
        return;
    }
    const int wip  = threadIdx.x >> 5;
    const int row  = blockIdx.x * 8 + wip;
    const unsigned lane = threadIdx.x & 31u;
    __shared__ float h1s[8][32];
    __shared__ float h2s[8][64];

    float lv[NCLS];
    const float* L = lab + row * NCLS;
#pragma unroll
    for (int c = 0; c < NCLS; ++c) lv[c] = L[c];

    {
        float a = eb1[lane];
#pragma unroll
        for (int c = 0; c < NCLS; ++c) a = fmaf(lv[c], ew1[lane * NCLS + c], a);
        h1s[wip][lane] = leaky(a);
    }
    __syncwarp();
#pragma unroll
    for (int j = 0; j < 2; ++j) {
        const int o = lane + 32 * j;
        float a = eb2[o];
#pragma unroll
        for (int i = 0; i < 32; ++i) a = fmaf(h1s[wip][i], ew2[o * 32 + i], a);
        h2s[wip][o] = leaky(a);
    }
    __syncwarp();
    if (lane < 2 * NQ) {
        float a = eb3[lane];
#pragma unroll
        for (int i = 0; i < 64; ++i) a = fmaf(h2s[wip][i], ew3[lane * 64 + i], a);
        g_angles[row * 2 * NQ + lane] = tanhf(a) * 3.14159265358979323846f;
    }
}

// =====================================================================
// Launch 2: quantum circuit, ONE warp per circuit (R15 structure).
// =====================================================================
__device__ __forceinline__ void qfac(float th, float ph, float cw, float sw,
                                     float2& f0, float2& f1)
{
    float ct, st, cp, sp;
    __sincosf(th, &st, &ct);
    __sincosf(ph, &sp, &cp);
    const float2 a0 = make_float2(ct * cp, -ct * sp);
    const float2 a1 = make_float2(st * cp,  st * sp);
    f0 = make_float2(fmaf(cw, a0.x, -sw * a1.x), fmaf(cw, a0.y, -sw * a1.y));
    f1 = make_float2(fmaf(sw, a0.x,  cw * a1.x), fmaf(sw, a0.y,  cw * a1.y));
}

template <int M>
__device__ __forceinline__ void ry_shear(u64 (&v)[32], u64 nt2, u64 s2)
{
#pragma unroll
    for (int r = 0; r < 32; ++r) {
        if (!(r & M)) {
            v[r]     = f2fma(nt2, v[r | M], v[r]);
            v[r | M] = f2fma(s2,  v[r],     v[r | M]);
            v[r]     = f2fma(nt2, v[r | M], v[r]);
        }
    }
}

template <int M>
__device__ __forceinline__ void ry_shear8(u64 (&v)[32], u64 nt2, u64 s2)
{
#pragma unroll
    for (int r = 0; r < 8; ++r) {
        if (!(r & M)) {
            v[r]     = f2fma(nt2, v[r | M], v[r]);
            v[r | M] = f2fma(s2,  v[r],     v[r | M]);
            v[r]     = f2fma(nt2, v[r | M], v[r]);
        }
    }
}

template <int MK>
__device__ __forceinline__ void ry_lane8(u64 (&v)[32], u64 c2, u64 s2, u64 ns2, unsigned lane)
{
    const u64 t2 = (lane & MK) ? s2 : ns2;
#pragma unroll
    for (int r = 0; r < 8; ++r) {
        const u64 p = __shfl_xor_sync(0xffffffffu, v[r], MK);
        v[r] = f2fma(t2, p, f2mul(c2, v[r]));
    }
}

__device__ __forceinline__ void wtranspose(u64* tp, u64 (&v)[32], unsigned lane)
{
#pragma unroll
    for (int r = 0; r < 32; ++r) tp[r * 33 + lane] = v[r];
    __syncwarp();
#pragma unroll
    for (int r = 0; r < 32; ++r) v[r] = tp[lane * 33 + r];
    __syncwarp();
}

__global__ void __launch_bounds__(128, 5) qsim_kernel(const float* __restrict__ noise)
{
    __shared__ u64 tb[4][32 * 33];
    const int tid = threadIdx.x;
    const int wib = tid >> 5;
    const unsigned lane = tid & 31u;
    const int w = blockIdx.x * 4 + wib;      // 0..8191
    const int b = w >> 2, g = w & 3;
    const float* nz = noise + b * NQ;
    const float* an = g_angles + b * 2 * NQ;
    const float* az = an + NQ;
    const float* wc = g_wc + g * DEPTH * NQ;
    const float* ws = g_ws + g * DEPTH * NQ;
    const float* wt = g_wt + g * DEPTH * NQ;
    u64* tp = tb[wib];

    float2 Lf;
    {
        float2 f0, f1;
        qfac(0.5f * (nz[5] + an[5]), 0.5f * az[5], wc[5], ws[5], f0, f1);
        Lf = ((lane >> 4) & 1u) ? f1 : f0;
#pragma unroll
        for (int q = 6; q <= 9; ++q) {
            qfac(0.5f * (nz[q] + an[q]), 0.5f * az[q], wc[q], ws[q], f0, f1);
            Lf = cmul(Lf, ((lane >> (9 - q)) & 1u) ? f1 : f0);
        }
    }
    float2 Lh[4];
    {
        float2 f0, f1, e0, e1;
        qfac(0.5f * (nz[0] + an[0]), 0.5f * az[0], wc[0], ws[0], f0, f1);
        qfac(0.5f * (nz[1] + an[1]), 0.5f * az[1], wc[1], ws[1], e0, e1);
        const float2 La = cmul(Lf, f0), Lb = cmul(Lf, f1);
        Lh[0] = cmul(La, e0); Lh[1] = cmul(La, e1);
        Lh[2] = cmul(Lb, e0); Lh[3] = cmul(Lb, e1);
    }
    float2 Rlo[8];
    {
        float2 f0, f1, e0, e1, d0, d1;
        qfac(0.5f * (nz[2] + an[2]), 0.5f * az[2], wc[2], ws[2], f0, f1);
        qfac(0.5f * (nz[3] + an[3]), 0.5f * az[3], wc[3], ws[3], e0, e1);
        qfac(0.5f * (nz[4] + an[4]), 0.5f * az[4], wc[4], ws[4], d0, d1);
        const float2 t0 = cmul(f0, e0), t1 = cmul(f0, e1),
                     t2 = cmul(f1, e0), t3 = cmul(f1, e1);
        Rlo[0] = cmul(t0, d0); Rlo[1] = cmul(t0, d1);
        Rlo[2] = cmul(t1, d0); Rlo[3] = cmul(t1, d1);
        Rlo[4] = cmul(t2, d0); Rlo[5] = cmul(t2, d1);
        Rlo[6] = cmul(t3, d0); Rlo[7] = cmul(t3, d1);
    }
    u64 v[32];
#pragma unroll
    for (int r = 0; r < 32; ++r) {
        const float2 a = cmul(Lh[r >> 3], Rlo[r & 7]);
        v[r] = pk2(a.x, a.y);
    }

    const u64 SGN = 0x8000000080000000ull;
    const unsigned pL = (unsigned)(__popc(lane & (lane >> 1)) & 1);
    const u64 mBase = pL ? SGN : 0ull;
    const u64 mOddA = mBase ^ (((lane >> 4) & 1u) ? SGN : 0ull);
    const u64 mHiB  = mBase ^ ((lane & 1u) ? SGN : 0ull);

#define CZA() { \
    _Pragma("unroll") \
    for (int r = 0; r < 32; ++r) { \
        const int srg = (__popc(r & (r >> 1)) & 1); \
        u64 m = (r & 1) ? mOddA : mBase; \
        if (srg) m ^= SGN; \
        v[r] ^= m; } }
#define CZB() { \
    _Pragma("unroll") \
    for (int r = 0; r < 32; ++r) { \
        const int srg = (__popc(r & (r >> 1)) & 1); \
        u64 m = (r & 16) ? mHiB : mBase; \
        if (srg) m ^= SGN; \
        v[r] ^= m; } }
#define ASIDE(lt_, ls_) { \
    ry_shear<16>(v, pk2(-(lt_)[0], -(lt_)[0]), pk2((ls_)[0], (ls_)[0])); \
    ry_shear<8> (v, pk2(-(lt_)[1], -(lt_)[1]), pk2((ls_)[1], (ls_)[1])); \
    ry_shear<4> (v, pk2(-(lt_)[2], -(lt_)[2]), pk2((ls_)[2], (ls_)[2])); \
    ry_shear<2> (v, pk2(-(lt_)[3], -(lt_)[3]), pk2((ls_)[3], (ls_)[3])); \
    ry_shear<1> (v, pk2(-(lt_)[4], -(lt_)[4]), pk2((ls_)[4], (ls_)[4])); }
#define BSIDE(lt_, ls_) { \
    ry_shear<16>(v, pk2(-(lt_)[5], -(lt_)[5]), pk2((ls_)[5], (ls_)[5])); \
    ry_shear<8> (v, pk2(-(lt_)[6], -(lt_)[6]), pk2((ls_)[6], (ls_)[6])); \
    ry_shear<4> (v, pk2(-(lt_)[7], -(lt_)[7]), pk2((ls_)[7], (ls_)[7])); \
    ry_shear<2> (v, pk2(-(lt_)[8], -(lt_)[8]), pk2((ls_)[8], (ls_)[8])); \
    ry_shear<1> (v, pk2(-(lt_)[9], -(lt_)[9]), pk2((ls_)[9], (ls_)[9])); }

    CZA()   // layer 0's CZ (RYs folded into prologue)

#pragma unroll 1
    for (int p = 0; p < 2; ++p) {
        const float* lsE = ws + (2 * p + 1) * NQ;
        const float* ltE = wt + (2 * p + 1) * NQ;
        const float* lsO = ws + (2 * p + 2) * NQ;
        const float* ltO = wt + (2 * p + 2) * NQ;

        ASIDE(ltE, lsE)
        wtranspose(tp, v, lane);
        BSIDE(ltE, lsE)
        CZB()

        BSIDE(ltO, lsO)
        wtranspose(tp, v, lane);
        ASIDE(ltO, lsO)
        CZA()
    }

    {   // layer 5 pruned
        const float* lc5 = wc + 5 * NQ;
        const float* ls5 = ws + 5 * NQ;
        const float* lt5 = wt + 5 * NQ;
        {
            const float cc = lc5[0], ss = ls5[0];
            const u64 c2 = pk2(cc, cc), ns2 = pk2(-ss, -ss);
#pragma unroll
            for (int r = 0; r < 16; ++r)
                v[r] = f2fma(ns2, v[r | 16], f2mul(c2, v[r]));
        }
        {
            const float cc = lc5[1], ss = ls5[1];
            const u64 c2 = pk2(cc, cc), ns2 = pk2(-ss, -ss);
#pragma unroll
            for (int r = 0; r < 8; ++r)
                v[r] = f2fma(ns2, v[r | 8], f2mul(c2, v[r]));
        }
        ry_shear8<4>(v, pk2(-lt5[2], -lt5[2]), pk2(ls5[2], ls5[2]));
        ry_shear8<2>(v, pk2(-lt5[3], -lt5[3]), pk2(ls5[3], ls5[3]));
        ry_shear8<1>(v, pk2(-lt5[4], -lt5[4]), pk2(ls5[4], ls5[4]));
#define RYL8(q, MK) { const float cc = lc5[q], ss = ls5[q]; \
                      ry_lane8<MK>(v, pk2(cc, cc), pk2(ss, ss), pk2(-ss, -ss), lane); }
        RYL8(5, 16) RYL8(6, 8) RYL8(7, 4) RYL8(8, 2) RYL8(9, 1)
#undef RYL8
    }
#undef ASIDE
#undef BSIDE
#undef CZA
#undef CZB

    float p[8];
    float mx = 0.f;
#pragma unroll
    for (int r = 0; r < 8; ++r) {
        const u64 sq = f2mul(v[r], v[r]);
        float x, y; upk2(x, y, sq);
        p[r] = x + y;
        mx = fmaxf(mx, p[r]);
    }
#pragma unroll
    for (int o = 16; o; o >>= 1) mx = fmaxf(mx, __shfl_xor_sync(0xffffffffu, mx, o));
    const float inv = 1.0f / mx;
    float* dst = g_qf + b * QOUT + g * PATCH;
#pragma unroll
    for (int r = 0; r < 8; ++r) dst[r * 32 + lane] = p[r] * inv;
}

// =====================================================================
// Launch 3: gemm1 split-K partial. 256 blocks = 64 row-tiles x 4 kc.
// Tile 32 rows x 128 cols x 256 k; microtile 4x4; double-buffered.
// =====================================================================
__global__ void __launch_bounds__(256) gemm1p_kernel(const float* __restrict__ W)
{
    __shared__ float xs[32][32];
    __shared__ float ws[32][128];
    const int rowBase = (blockIdx.x >> 2) * 32;
    const int kc      = (blockIdx.x & 3) * 256;
    const int tid = threadIdx.x;
    const int ty = tid >> 5, tx = tid & 31;

    const int xrow = tid & 31,  xk4 = (tid >> 5) * 4;
    const int wcol = tid >> 1,  wk0 = (tid & 1) * 16;

    float4 xp;
    float2 wp[8];
#define LOADX(kb) { \
    xp = *reinterpret_cast<const float4*>(&g_qf[(rowBase + xrow) * QOUT + kc + (kb) + xk4]); }
#define LOADW(kb) { \
    _Pragma("unroll") \
    for (int u = 0; u < 8; ++u) \
        wp[u] = *reinterpret_cast<const float2*>(&W[wcol * 1034 + kc + (kb) + wk0 + u * 2]); }

    LOADX(0) LOADW(0)

    float acc[4][4];
#pragma unroll
    for (int i = 0; i < 4; ++i)
#pragma unroll
        for (int j = 0; j < 4; ++j) acc[i][j] = 0.f;

    for (int kb = 0; kb < 256; kb += 32) {
        __syncthreads();
        xs[xk4 + 0][xrow] = xp.x; xs[xk4 + 1][xrow] = xp.y;
        xs[xk4 + 2][xrow] = xp.z; xs[xk4 + 3][xrow] = xp.w;
#pragma unroll
        for (int u = 0; u < 8; ++u) {
            ws[wk0 + u * 2 + 0][wcol] = wp[u].x;
            ws[wk0 + u * 2 + 1][wcol] = wp[u].y;
        }
        __syncthreads();
        if (kb + 32 < 256) { LOADX(kb + 32) LOADW(kb + 32) }
#pragma unroll
        for (int kk = 0; kk < 32; ++kk) {
            const float4 A = *reinterpret_cast<const float4*>(&xs[kk][ty * 4]);
            const float4 B = *reinterpret_cast<const float4*>(&ws[kk][tx * 4]);
            const float a[4] = {A.x, A.y, A.z, A.w};
            const float bb[4] = {B.x, B.y, B.z, B.w};
#pragma unroll
            for (int i = 0; i < 4; ++i)
#pragma unroll
                for (int j = 0; j < 4; ++j) acc[i][j] = fmaf(a[i], bb[j], acc[i][j]);
        }
    }
#undef LOADX
#undef LOADW

    float* dst = g_p1[blockIdx.x & 3];
#pragma unroll
    for (int i = 0; i < 4; ++i) {
        const int row = rowBase + ty * 4 + i;
        float4 vv = make_float4(acc[i][0], acc[i][1], acc[i][2], acc[i][3]);
        *reinterpret_cast<float4*>(&dst[row * 128 + tx * 4]) = vv;
    }
}

// =====================================================================
// Launch 4: reduce1 (128 blocks x 16 rows) + BN1 partials (128).
// =====================================================================
__global__ void __launch_bounds__(256) reduce1_kernel(
    const float* __restrict__ lab, const float* __restrict__ bias)
{
    __shared__ float sh1[8][128];
    __shared__ float sh2[8][128];
    const int tid = threadIdx.x;
    const int cq = tid & 31, cg = cq * 4, rg = tid >> 5;

    const float4 bv = *reinterpret_cast<const float4*>(&bias[cg]);
    float4 wt[NCLS];
#pragma unroll
    for (int c = 0; c < NCLS; ++c)
        wt[c] = *reinterpret_cast<const float4*>(&g_wtail[c][cg]);

    float a1x = 0.f, a1y = 0.f, a1z = 0.f, a1w = 0.f;
    float a2x = 0.f, a2y = 0.f, a2z = 0.f, a2w = 0.f;
#pragma unroll
    for (int rr = 0; rr < 2; ++rr) {
        const int row = blockIdx.x * 16 + rr * 8 + rg;
        float4 s = *reinterpret_cast<const float4*>(&g_p1[0][row * 128 + cg]);
        const float4 s1 = *reinterpret_cast<const float4*>(&g_p1[1][row * 128 + cg]);
        const float4 s2 = *reinterpret_cast<const float4*>(&g_p1[2][row * 128 + cg]);
        const float4 s3 = *reinterpret_cast<const float4*>(&g_p1[3][row * 128 + cg]);
        s.x += s1.x + s2.x + s3.x + bv.x;  s.y += s1.y + s2.y + s3.y + bv.y;
        s.z += s1.z + s2.z + s3.z + bv.z;  s.w += s1.w + s2.w + s3.w + bv.w;
#pragma unroll
        for (int c = 0; c < NCLS; ++c) {
            const float lv = lab[row * NCLS + c];
            s.x = fmaf(lv, wt[c].x, s.x); s.y = fmaf(lv, wt[c].y, s.y);
            s.z = fmaf(lv, wt[c].z, s.z); s.w = fmaf(lv, wt[c].w, s.w);
        }
        s.x = leaky(s.x); s.y = leaky(s.y); s.z = leaky(s.z); s.w = leaky(s.w);
        *reinterpret_cast<float4*>(&g_y1[row * 128 + cg]) = s;
        a1x += s.x; a1y += s.y; a1z += s.z; a1w += s.w;
        a2x = fmaf(s.x, s.x, a2x); a2y = fmaf(s.y, s.y, a2y);
        a2z = fmaf(s.z, s.z, a2z); a2w = fmaf(s.w, s.w, a2w);
    }
    sh1[rg][cg + 0] = a1x; sh1[rg][cg + 1] = a1y; sh1[rg][cg + 2] = a1z; sh1[rg][cg + 3] = a1w;
    sh2[rg][cg + 0] = a2x; sh2[rg][cg + 1] = a2y; sh2[rg][cg + 2] = a2z; sh2[rg][cg + 3] = a2w;
    __syncthreads();
    if (tid < 128) {
        float t1 = 0.f, t2 = 0.f;
#pragma unroll
        for (int r = 0; r < 8; ++r) { t1 += sh1[r][tid]; t2 += sh2[r][tid]; }
        g_ps1[blockIdx.x][tid] = t1;
        g_pq1[blockIdx.x][tid] = t2;
    }
}

// =====================================================================
// Launch 5: gemm2 (BN1 finalize fused; BN2 partials emitted)
// =====================================================================
__global__ void __launch_bounds__(256) gemm2_kernel(
    const float* __restrict__ W, const float* __restrict__ bias,
    const float* __restrict__ gamma, const float* __restrict__ beta)
{
    __shared__ float xs[32][32];
    __shared__ float ws[32][128];
    __shared__ float bns[128], bnh[128];
    __shared__ float p1s[8][128];
    __shared__ float p2s[8][128];
    const int rowBase = blockIdx.x * 32;
    const int tid = threadIdx.x;
    const int ty = tid >> 5, tx = tid & 31;

    if (tid < 128) {
        float s1 = 0.f, s2 = 0.f;
#pragma unroll 4
        for (int b = 0; b < 128; ++b) { s1 += g_ps1[b][tid]; s2 += g_pq1[b][tid]; }
        const float mu   = s1 * (1.f / BATCH);
        const float var  = s2 * (1.f / BATCH) - mu * mu;
        const float rstd = rsqrtf(var + 1e-5f);
        const float sc = gamma[tid] * rstd;
        bns[tid] = sc; bnh[tid] = beta[tid] - mu * sc;
    }
    __syncthreads();

    float acc[4][4];
#pragma unroll
    for (int i = 0; i < 4; ++i)
#pragma unroll
        for (int j = 0; j < 4; ++j) acc[i][j] = 0.f;

    for (int kb = 0; kb < 128; kb += 32) {
        __syncthreads();
        {
            const int row = tid & 31;
            const int k4  = (tid >> 5) * 4;
            const float4 vv = *reinterpret_cast<const float4*>(&g_y1[(rowBase + row) * 128 + kb + k4]);
            xs[k4 + 0][row] = fmaf(vv.x, bns[kb + k4 + 0], bnh[kb + k4 + 0]);
            xs[k4 + 1][row] = fmaf(vv.y, bns[kb + k4 + 1], bnh[kb + k4 + 1]);
            xs[k4 + 2][row] = fmaf(vv.z, bns[kb + k4 + 2], bnh[kb + k4 + 2]);
            xs[k4 + 3][row] = fmaf(vv.w, bns[kb + k4 + 3], bnh[kb + k4 + 3]);
        }
        {
            const int col = tid >> 1;
            const int k0  = (tid & 1) * 16;
#pragma unroll
            for (int u = 0; u < 16; u += 4) {
                const float4 vv = *reinterpret_cast<const float4*>(&W[col * 128 + kb + k0 + u]);
                ws[k0 + u + 0][col] = vv.x; ws[k0 + u + 1][col] = vv.y;
                ws[k0 + u + 2][col] = vv.z; ws[k0 + u + 3][col] = vv.w;
            }
        }
        __syncthreads();
#pragma unroll
        for (int kk = 0; kk < 32; ++kk) {
            const float4 A = *reinterpret_cast<const float4*>(&xs[kk][ty * 4]);
            const float4 B = *reinterpret_cast<const float4*>(&ws[kk][tx * 4]);
            const float a[4] = {A.x, A.y, A.z, A.w};
            const float bb[4] = {B.x, B.y, B.z, B.w};
#pragma unroll
            for (int i = 0; i < 4; ++i)
#pragma unroll
                for (int j = 0; j < 4; ++j) acc[i][j] = fmaf(a[i], bb[j], acc[i][j]);
        }
    }
    const float4 bv = *reinterpret_cast<const float4*>(&bias[tx * 4]);
    float c1[4] = {0.f, 0.f, 0.f, 0.f}, c2[4] = {0.f, 0.f, 0.f, 0.f};
#pragma unroll
    for (int i = 0; i < 4; ++i) {
        const int row = rowBase + ty * 4 + i;
        float4 vv = make_float4(leaky(acc[i][0] + bv.x), leaky(acc[i][1] + bv.y),
                                leaky(acc[i][2] + bv.z), leaky(acc[i][3] + bv.w));
        *reinterpret_cast<float4*>(&g_y2[row * 128 + tx * 4]) = vv;
        c1[0] += vv.x; c1[1] += vv.y; c1[2] += vv.z; c1[3] += vv.w;
        c2[0] = fmaf(vv.x, vv.x, c2[0]); c2[1] = fmaf(vv.y, vv.y, c2[1]);
        c2[2] = fmaf(vv.z, vv.z, c2[2]); c2[3] = fmaf(vv.w, vv.w, c2[3]);
    }
#pragma unroll
    for (int j = 0; j < 4; ++j) { p1s[ty][tx * 4 + j] = c1[j]; p2s[ty][tx * 4 + j] = c2[j]; }
    __syncthreads();
    if (tid < 128) {
        float a1 = 0.f, a2 = 0.f;
#pragma unroll
        for (int r = 0; r < 8; ++r) { a1 += p1s[r][tid]; a2 += p2s[r][tid]; }
        g_ps2[blockIdx.x][tid] = a1;
        g_pq2[blockIdx.x][tid] = a2;
    }
}

// =====================================================================
// Launch 6: gemm3 (BN2 finalize fused)
// =====================================================================
__global__ void __launch_bounds__(256) gemm3_kernel(
    const float* __restrict__ W, const float* __restrict__ bias,
    const float* __restrict__ gamma, const float* __restrict__ beta,
    float* __restrict__ out)
{
    __shared__ float xs[32][32];
    __shared__ float ws[32][64];
    __shared__ float bns[128], bnh[128];
    const int rowBase = blockIdx.x * 32;
    const int tid = threadIdx.x;
    const int ty = tid >> 4;
    const int tx = tid & 15;

    if (tid < 128) {
        float s1 = 0.f, s2 = 0.f;
#pragma unroll
        for (int b = 0; b < 64; ++b) { s1 += g_ps2[b][tid]; s2 += g_pq2[b][tid]; }
        const float mu   = s1 * (1.f / BATCH);
        const float var  = s2 * (1.f / BATCH) - mu * mu;
        const float rstd = rsqrtf(var + 1e-5f);
        const float sc = gamma[tid] * rstd;
        bns[tid] = sc; bnh[tid] = beta[tid] - mu * sc;
    }
    __syncthreads();

    float acc[2][4];
#pragma unroll
    for (int i = 0; i < 2; ++i)
#pragma unroll
        for (int j = 0; j < 4; ++j) acc[i][j] = 0.f;

    for (int kb = 0; kb < 128; kb += 32) {
        __syncthreads();
        {
            const int row = tid & 31;
            const int k4  = (tid >> 5) * 4;
            const float4 vv = *reinterpret_cast<const float4*>(&g_y2[(rowBase + row) * 128 + kb + k4]);
            xs[k4 + 0][row] = fmaf(vv.x, bns[kb + k4 + 0], bnh[kb + k4 + 0]);
            xs[k4 + 1][row] = fmaf(vv.y, bns[kb + k4 + 1], bnh[kb + k4 + 1]);
            xs[k4 + 2][row] = fmaf(vv.z, bns[kb + k4 + 2], bnh[kb + k4 + 2]);
            xs[k4 + 3][row] = fmaf(vv.w, bns[kb + k4 + 3], bnh[kb + k4 + 3]);
        }
        {
            const int col = tid >> 2;
            const int k0  = (tid & 3) * 8;
#pragma unroll
            for (int u = 0; u < 8; u += 4) {
                const float4 vv = *reinterpret_cast<const float4*>(&W[col * 128 + kb + k0 + u]);
                ws[k0 + u + 0][col] = vv.x; ws[k0 + u + 1][col] = vv.y;
                ws[k0 + u + 2][col] = vv.z; ws[k0 + u + 3][col] = vv.w;
            }
        }
        __syncthreads();
#pragma unroll
        for (int kk = 0; kk < 32; ++kk) {
            const float2 A = *reinterpret_cast<const float2*>(&xs[kk][ty * 2]);
            const float4 B = *reinterpret_cast<const float4*>(&ws[kk][tx * 4]);
            const float a[2] = {A.x, A.y};
            const float bb[4] = {B.x, B.y, B.z, B.w};
#pragma unroll
            for (int i = 0; i < 2; ++i)
#pragma unroll
                for (int j = 0; j < 4; ++j) acc[i][j] = fmaf(a[i], bb[j], acc[i][j]);
        }
    }
    const float4 bv = *reinterpret_cast<const float4*>(&bias[tx * 4]);
#pragma unroll
    for (int i = 0; i < 2; ++i) {
        const int row = rowBase + ty * 2 + i;
        float4 vv = make_float4(tanhf(acc[i][0] + bv.x), tanhf(acc[i][1] + bv.y),
                                tanhf(acc[i][2] + bv.z), tanhf(acc[i][3] + bv.w));
        *reinterpret_cast<float4*>(&out[row * 64 + tx * 4]) = vv;
    }
}

// =====================================================================
extern "C" void kernel_launch(void* const* d_in, const int* in_sizes, int n_in,
                              void* d_out, int out_size)
{
    const float* noise  = (const float*)d_in[0];
    const float* labels = (const float*)d_in[1];
    const float* qparams= (const float*)d_in[2];
    const float* ew1 = (const float*)d_in[3];  const float* eb1 = (const float*)d_in[4];
    const float* ew2 = (const float*)d_in[5];  const float* eb2 = (const float*)d_in[6];
    const float* ew3 = (const float*)d_in[7];  const float* eb3 = (const float*)d_in[8];
    const float* pw1 = (const float*)d_in[9];  const float* pb1 = (const float*)d_in[10];
    const float* g1  = (const float*)d_in[11]; const float* be1 = (const float*)d_in[12];
    const float* pw2 = (const float*)d_in[13]; const float* pb2 = (const float*)d_in[14];
    const float* g2  = (const float*)d_in[15]; const float* be2 = (const float*)d_in[16];
    const float* pw3 = (const float*)d_in[17]; const float* pb3 = (const float*)d_in[18];
    float* out = (float*)d_out;

    embed_kernel<<<257, 256>>>(labels, qparams, pw1, ew1, eb1, ew2, eb2, ew3, eb3);  // 1
    qsim_kernel<<<BATCH * NGEN / 4, 128>>>(noise);      // 2
    gemm1p_kernel<<<256, 256>>>(pw1);                   // 3
    reduce1_kernel<<<128, 256>>>(labels, pb1);          // 4
    gemm2_kernel<<<64, 256>>>(pw2, pb2, g1, be1);       // 5
    gemm3_kernel<<<64, 256>>>(pw3, pb3, g2, be2, out);  // 6
}

// round 17
// speedup vs baseline: 1.0299x; 1.0299x over previous
#include <cuda_runtime.h>
#include <math.h>

#define BATCH 2048
#define NQ    10
#define NGEN  4
#define DEPTH 6
#define PATCH 256
#define QOUT  1024
#define NCLS  10

typedef unsigned long long u64;

// ---------------- scratch (device globals; no allocation) ----------------
__device__ __align__(256) float g_angles[BATCH * 2 * NQ];   // (B,20)
__device__ __align__(256) float g_qf[BATCH * QOUT];         // (B,1024)
__device__ __align__(256) float g_y1[BATCH * 128];
__device__ __align__(256) float g_y2[BATCH * 128];
__device__ __align__(16)  float g_wc[NGEN * DEPTH * NQ];    // cos(th/2)
__device__ __align__(16)  float g_ws[NGEN * DEPTH * NQ];    // sin(th/2)
__device__ __align__(16)  float g_wt[NGEN * DEPTH * NQ];    // tan(th/4)
__device__ __align__(256) float g_ps1[128][128], g_pq1[128][128]; // BN1 partials
__device__ __align__(256) float g_ps2[64][128],  g_pq2[64][128];  // BN2 partials
__device__ __align__(256) float g_p1[4][BATCH * 128];  // gemm1 split-K partials
__device__ __align__(256) float g_wtail[NCLS][128];    // pw1 label-tail, transposed

__device__ __forceinline__ float leaky(float x) { return x > 0.f ? x : 0.2f * x; }

// ---------------- packed f32x2 helpers ----------------
__device__ __forceinline__ u64 pk2(float lo, float hi) {
    u64 r; asm("mov.b64 %0,{%1,%2};" : "=l"(r) : "f"(lo), "f"(hi)); return r;
}
__device__ __forceinline__ void upk2(float& lo, float& hi, u64 v) {
    asm("mov.b64 {%0,%1},%2;" : "=f"(lo), "=f"(hi) : "l"(v));
}
__device__ __forceinline__ u64 f2fma(u64 a, u64 b, u64 c) {
    u64 d; asm("fma.rn.f32x2 %0,%1,%2,%3;" : "=l"(d) : "l"(a), "l"(b), "l"(c)); return d;
}
__device__ __forceinline__ u64 f2mul(u64 a, u64 b) {
    u64 d; asm("mul.rn.f32x2 %0,%1,%2;" : "=l"(d) : "l"(a), "l"(b)); return d;
}
__device__ __forceinline__ float2 cmul(float2 a, float2 b) {
    return make_float2(fmaf(a.x, b.x, -a.y * b.y), fmaf(a.x, b.y, a.y * b.x));
}

// =====================================================================
// Launch 1: embedding MLP (blocks 0..255) + table precompute (block 256)
// =====================================================================
__global__ void __launch_bounds__(256) embed_kernel(
    const float* __restrict__ lab, const float* __restrict__ qp,
    const float* __restrict__ pw1,
    const float* __restrict__ ew1, const float* __restrict__ eb1,
    const float* __restrict__ ew2, const float* __restrict__ eb2,
    const float* __restrict__ ew3, const float* __restrict__ eb3)
{
    if (blockIdx.x == 256) {
        const int i = threadIdx.x;
        if (i < NGEN * DEPTH * NQ) {
            float s, c; __sincosf(0.5f * qp[i], &s, &c);
            g_wc[i] = c; g_ws[i] = s;
            g_wt[i] = __fdividef(s, 1.f + c);      // tan(th/4), th in [0,1)
        }
        if (i < 128) {
#pragma unroll
            for (int c = 0; c < NCLS; ++c)
                g_wtail[c][i] = pw1[i * 1034 + QOUT + c];
        }
        return;
    }
    const int wip  = threadIdx.x >> 5;
    const int row  = blockIdx.x * 8 + wip;
    const unsigned lane = threadIdx.x & 31u;
    __shared__ float h1s[8][32];
    __shared__ float h2s[8][64];

    float lv[NCLS];
    const float* L = lab + row * NCLS;
#pragma unroll
    for (int c = 0; c < NCLS; ++c) lv[c] = L[c];

    {
        float a = eb1[lane];
#pragma unroll
        for (int c = 0; c < NCLS; ++c) a = fmaf(lv[c], ew1[lane * NCLS + c], a);
        h1s[wip][lane] = leaky(a);
    }
    __syncwarp();
#pragma unroll
    for (int j = 0; j < 2; ++j) {
        const int o = lane + 32 * j;
        float a = eb2[o];
#pragma unroll
        for (int i = 0; i < 32; ++i) a = fmaf(h1s[wip][i], ew2[o * 32 + i], a);
        h2s[wip][o] = leaky(a);
    }
    __syncwarp();
    if (lane < 2 * NQ) {
        float a = eb3[lane];
#pragma unroll
        for (int i = 0; i < 64; ++i) a = fmaf(h2s[wip][i], ew3[lane * 64 + i], a);
        g_angles[row * 2 * NQ + lane] = tanhf(a) * 3.14159265358979323846f;
    }
}

// =====================================================================
// Launch 2: quantum circuit, ONE warp per circuit (R15 structure).
// =====================================================================
__device__ __forceinline__ void qfac(float th, float ph, float cw, float sw,
                                     float2& f0, float2& f1)
{
    float ct, st, cp, sp;
    __sincosf(th, &st, &ct);
    __sincosf(ph, &sp, &cp);
    const float2 a0 = make_float2(ct * cp, -ct * sp);
    const float2 a1 = make_float2(st * cp,  st * sp);
    f0 = make_float2(fmaf(cw, a0.x, -sw * a1.x), fmaf(cw, a0.y, -sw * a1.y));
    f1 = make_float2(fmaf(sw, a0.x,  cw * a1.x), fmaf(sw, a0.y,  cw * a1.y));
}

template <int M>
__device__ __forceinline__ void ry_shear(u64 (&v)[32], u64 nt2, u64 s2)
{
#pragma unroll
    for (int r = 0; r < 32; ++r) {
        if (!(r & M)) {
            v[r]     = f2fma(nt2, v[r | M], v[r]);
            v[r | M] = f2fma(s2,  v[r],     v[r | M]);
            v[r]     = f2fma(nt2, v[r | M], v[r]);
        }
    }
}

template <int M>
__device__ __forceinline__ void ry_shear8(u64 (&v)[32], u64 nt2, u64 s2)
{
#pragma unroll
    for (int r = 0; r < 8; ++r) {
        if (!(r & M)) {
            v[r]     = f2fma(nt2, v[r | M], v[r]);
            v[r | M] = f2fma(s2,  v[r],     v[r | M]);
            v[r]     = f2fma(nt2, v[r | M], v[r]);
        }
    }
}

template <int MK>
__device__ __forceinline__ void ry_lane8(u64 (&v)[32], u64 c2, u64 s2, u64 ns2, unsigned lane)
{
    const u64 t2 = (lane & MK) ? s2 : ns2;
#pragma unroll
    for (int r = 0; r < 8; ++r) {
        const u64 p = __shfl_xor_sync(0xffffffffu, v[r], MK);
        v[r] = f2fma(t2, p, f2mul(c2, v[r]));
    }
}

__device__ __forceinline__ void wtranspose(u64* tp, u64 (&v)[32], unsigned lane)
{
#pragma unroll
    for (int r = 0; r < 32; ++r) tp[r * 33 + lane] = v[r];
    __syncwarp();
#pragma unroll
    for (int r = 0; r < 32; ++r) v[r] = tp[lane * 33 + r];
    __syncwarp();
}

__global__ void __launch_bounds__(128, 5) qsim_kernel(const float* __restrict__ noise)
{
    __shared__ u64 tb[4][32 * 33];
    const int tid = threadIdx.x;
    const int wib = tid >> 5;
    const unsigned lane = tid & 31u;
    const int w = blockIdx.x * 4 + wib;      // 0..8191
    const int b = w >> 2, g = w & 3;
    const float* nz = noise + b * NQ;
    const float* an = g_angles + b * 2 * NQ;
    const float* az = an + NQ;
    const float* wc = g_wc + g * DEPTH * NQ;
    const float* ws = g_ws + g * DEPTH * NQ;
    const float* wt = g_wt + g * DEPTH * NQ;
    u64* tp = tb[wib];

    float2 Lf;
    {
        float2 f0, f1;
        qfac(0.5f * (nz[5] + an[5]), 0.5f * az[5], wc[5], ws[5], f0, f1);
        Lf = ((lane >> 4) & 1u) ? f1 : f0;
#pragma unroll
        for (int q = 6; q <= 9; ++q) {
            qfac(0.5f * (nz[q] + an[q]), 0.5f * az[q], wc[q], ws[q], f0, f1);
            Lf = cmul(Lf, ((lane >> (9 - q)) & 1u) ? f1 : f0);
        }
    }
    float2 Lh[4];
    {
        float2 f0, f1, e0, e1;
        qfac(0.5f * (nz[0] + an[0]), 0.5f * az[0], wc[0], ws[0], f0, f1);
        qfac(0.5f * (nz[1] + an[1]), 0.5f * az[1], wc[1], ws[1], e0, e1);
        const float2 La = cmul(Lf, f0), Lb = cmul(Lf, f1);
        Lh[0] = cmul(La, e0); Lh[1] = cmul(La, e1);
        Lh[2] = cmul(Lb, e0); Lh[3] = cmul(Lb, e1);
    }
    float2 Rlo[8];
    {
        float2 f0, f1, e0, e1, d0, d1;
        qfac(0.5f * (nz[2] + an[2]), 0.5f * az[2], wc[2], ws[2], f0, f1);
        qfac(0.5f * (nz[3] + an[3]), 0.5f * az[3], wc[3], ws[3], e0, e1);
        qfac(0.5f * (nz[4] + an[4]), 0.5f * az[4], wc[4], ws[4], d0, d1);
        const float2 t0 = cmul(f0, e0), t1 = cmul(f0, e1),
                     t2 = cmul(f1, e0), t3 = cmul(f1, e1);
        Rlo[0] = cmul(t0, d0); Rlo[1] = cmul(t0, d1);
        Rlo[2] = cmul(t1, d0); Rlo[3] = cmul(t1, d1);
        Rlo[4] = cmul(t2, d0); Rlo[5] = cmul(t2, d1);
        Rlo[6] = cmul(t3, d0); Rlo[7] = cmul(t3, d1);
    }
    u64 v[32];
#pragma unroll
    for (int r = 0; r < 32; ++r) {
        const float2 a = cmul(Lh[r >> 3], Rlo[r & 7]);
        v[r] = pk2(a.x, a.y);
    }

    const u64 SGN = 0x8000000080000000ull;
    const unsigned pL = (unsigned)(__popc(lane & (lane >> 1)) & 1);
    const u64 mBase = pL ? SGN : 0ull;
    const u64 mOddA = mBase ^ (((lane >> 4) & 1u) ? SGN : 0ull);
    const u64 mHiB  = mBase ^ ((lane & 1u) ? SGN : 0ull);

#define CZA() { \
    _Pragma("unroll") \
    for (int r = 0; r < 32; ++r) { \
        const int srg = (__popc(r & (r >> 1)) & 1); \
        u64 m = (r & 1) ? mOddA : mBase; \
        if (srg) m ^= SGN; \
        v[r] ^= m; } }
#define CZB() { \
    _Pragma("unroll") \
    for (int r = 0; r < 32; ++r) { \
        const int srg = (__popc(r & (r >> 1)) & 1); \
        u64 m = (r & 16) ? mHiB : mBase; \
        if (srg) m ^= SGN; \
        v[r] ^= m; } }
#define ASIDE(lt_, ls_) { \
    ry_shear<16>(v, pk2(-(lt_)[0], -(lt_)[0]), pk2((ls_)[0], (ls_)[0])); \
    ry_shear<8> (v, pk2(-(lt_)[1], -(lt_)[1]), pk2((ls_)[1], (ls_)[1])); \
    ry_shear<4> (v, pk2(-(lt_)[2], -(lt_)[2]), pk2((ls_)[2], (ls_)[2])); \
    ry_shear<2> (v, pk2(-(lt_)[3], -(lt_)[3]), pk2((ls_)[3], (ls_)[3])); \
    ry_shear<1> (v, pk2(-(lt_)[4], -(lt_)[4]), pk2((ls_)[4], (ls_)[4])); }
#define BSIDE(lt_, ls_) { \
    ry_shear<16>(v, pk2(-(lt_)[5], -(lt_)[5]), pk2((ls_)[5], (ls_)[5])); \
    ry_shear<8> (v, pk2(-(lt_)[6], -(lt_)[6]), pk2((ls_)[6], (ls_)[6])); \
    ry_shear<4> (v, pk2(-(lt_)[7], -(lt_)[7]), pk2((ls_)[7], (ls_)[7])); \
    ry_shear<2> (v, pk2(-(lt_)[8], -(lt_)[8]), pk2((ls_)[8], (ls_)[8])); \
    ry_shear<1> (v, pk2(-(lt_)[9], -(lt_)[9]), pk2((ls_)[9], (ls_)[9])); }

    CZA()   // layer 0's CZ (RYs folded into prologue)

#pragma unroll 1
    for (int p = 0; p < 2; ++p) {
        const float* lsE = ws + (2 * p + 1) * NQ;
        const float* ltE = wt + (2 * p + 1) * NQ;
        const float* lsO = ws + (2 * p + 2) * NQ;
        const float* ltO = wt + (2 * p + 2) * NQ;

        ASIDE(ltE, lsE)
        wtranspose(tp, v, lane);
        BSIDE(ltE, lsE)
        CZB()

        BSIDE(ltO, lsO)
        wtranspose(tp, v, lane);
        ASIDE(ltO, lsO)
        CZA()
    }

    {   // layer 5 pruned
        const float* lc5 = wc + 5 * NQ;
        const float* ls5 = ws + 5 * NQ;
        const float* lt5 = wt + 5 * NQ;
        {
            const float cc = lc5[0], ss = ls5[0];
            const u64 c2 = pk2(cc, cc), ns2 = pk2(-ss, -ss);
#pragma unroll
            for (int r = 0; r < 16; ++r)
                v[r] = f2fma(ns2, v[r | 16], f2mul(c2, v[r]));
        }
        {
            const float cc = lc5[1], ss = ls5[1];
            const u64 c2 = pk2(cc, cc), ns2 = pk2(-ss, -ss);
#pragma unroll
            for (int r = 0; r < 8; ++r)
                v[r] = f2fma(ns2, v[r | 8], f2mul(c2, v[r]));
        }
        ry_shear8<4>(v, pk2(-lt5[2], -lt5[2]), pk2(ls5[2], ls5[2]));
        ry_shear8<2>(v, pk2(-lt5[3], -lt5[3]), pk2(ls5[3], ls5[3]));
        ry_shear8<1>(v, pk2(-lt5[4], -lt5[4]), pk2(ls5[4], ls5[4]));
#define RYL8(q, MK) { const float cc = lc5[q], ss = ls5[q]; \
                      ry_lane8<MK>(v, pk2(cc, cc), pk2(ss, ss), pk2(-ss, -ss), lane); }
        RYL8(5, 16) RYL8(6, 8) RYL8(7, 4) RYL8(8, 2) RYL8(9, 1)
#undef RYL8
    }
#undef ASIDE
#undef BSIDE
#undef CZA
#undef CZB

    float p[8];
    float mx = 0.f;
#pragma unroll
    for (int r = 0; r < 8; ++r) {
        const u64 sq = f2mul(v[r], v[r]);
        float x, y; upk2(x, y, sq);
        p[r] = x + y;
        mx = fmaxf(mx, p[r]);
    }
#pragma unroll
    for (int o = 16; o; o >>= 1) mx = fmaxf(mx, __shfl_xor_sync(0xffffffffu, mx, o));
    const float inv = 1.0f / mx;
    float* dst = g_qf + b * QOUT + g * PATCH;
#pragma unroll
    for (int r = 0; r < 8; ++r) dst[r * 32 + lane] = p[r] * inv;
}

// =====================================================================
// Launch 3: gemm1 split-K partial (R15 config: 128 blocks = 32 row-tiles
// x 4 kc; 64 rows x 128 cols; microtile 8x4; double-buffered).
// =====================================================================
__global__ void __launch_bounds__(256) gemm1p_kernel(const float* __restrict__ W)
{
    __shared__ float xs[32][64];
    __shared__ float ws[32][128];
    const int rowBase = (blockIdx.x >> 2) * 64;
    const int kc      = (blockIdx.x & 3) * 256;
    const int tid = threadIdx.x;
    const int ty = tid >> 5, tx = tid & 31;

    const int xrow0 = tid & 63,          xk40 = (tid >> 6) * 4;
    const int xrow1 = (tid + 256) & 63,  xk41 = ((tid + 256) >> 6) * 4;
    const int wcol  = tid >> 1,          wk0  = (tid & 1) * 16;

    float4 xp0, xp1;
    float2 wp[8];
#define LOADX(kb) { \
    xp0 = *reinterpret_cast<const float4*>(&g_qf[(rowBase + xrow0) * QOUT + kc + (kb) + xk40]); \
    xp1 = *reinterpret_cast<const float4*>(&g_qf[(rowBase + xrow1) * QOUT + kc + (kb) + xk41]); }
#define LOADW(kb) { \
    _Pragma("unroll") \
    for (int u = 0; u < 8; ++u) \
        wp[u] = *reinterpret_cast<const float2*>(&W[wcol * 1034 + kc + (kb) + wk0 + u * 2]); }

    LOADX(0) LOADW(0)

    float acc[8][4];
#pragma unroll
    for (int i = 0; i < 8; ++i)
#pragma unroll
        for (int j = 0; j < 4; ++j) acc[i][j] = 0.f;

    for (int kb = 0; kb < 256; kb += 32) {
        __syncthreads();
        xs[xk40 + 0][xrow0] = xp0.x; xs[xk40 + 1][xrow0] = xp0.y;
        xs[xk40 + 2][xrow0] = xp0.z; xs[xk40 + 3][xrow0] = xp0.w;
        xs[xk41 + 0][xrow1] = xp1.x; xs[xk41 + 1][xrow1] = xp1.y;
        xs[xk41 + 2][xrow1] = xp1.z; xs[xk41 + 3][xrow1] = xp1.w;
#pragma unroll
        for (int u = 0; u < 8; ++u) {
            ws[wk0 + u * 2 + 0][wcol] = wp[u].x;
            ws[wk0 + u * 2 + 1][wcol] = wp[u].y;
        }
        __syncthreads();
        if (kb + 32 < 256) { LOADX(kb + 32) LOADW(kb + 32) }
#pragma unroll
        for (int kk = 0; kk < 32; ++kk) {
            const float4 A0 = *reinterpret_cast<const float4*>(&xs[kk][ty * 8]);
            const float4 A1 = *reinterpret_cast<const float4*>(&xs[kk][ty * 8 + 4]);
            const float4 B  = *reinterpret_cast<const float4*>(&ws[kk][tx * 4]);
            const float a[8] = {A0.x, A0.y, A0.z, A0.w, A1.x, A1.y, A1.z, A1.w};
            const float bb[4] = {B.x, B.y, B.z, B.w};
#pragma unroll
            for (int i = 0; i < 8; ++i)
#pragma unroll
                for (int j = 0; j < 4; ++j) acc[i][j] = fmaf(a[i], bb[j], acc[i][j]);
        }
    }
#undef LOADX
#undef LOADW

    float* dst = g_p1[blockIdx.x & 3];
#pragma unroll
    for (int i = 0; i < 8; ++i) {
        const int row = rowBase + ty * 8 + i;
        float4 vv = make_float4(acc[i][0], acc[i][1], acc[i][2], acc[i][3]);
        *reinterpret_cast<float4*>(&dst[row * 128 + tx * 4]) = vv;
    }
}

// =====================================================================
// Launch 4: reduce1 (128 blocks x 16 rows) + BN1 partials (128).
// =====================================================================
__global__ void __launch_bounds__(256) reduce1_kernel(
    const float* __restrict__ lab, const float* __restrict__ bias)
{
    __shared__ float sh1[8][128];
    __shared__ float sh2[8][128];
    const int tid = threadIdx.x;
    const int cq = tid & 31, cg = cq * 4, rg = tid >> 5;

    const float4 bv = *reinterpret_cast<const float4*>(&bias[cg]);
    float4 wt[NCLS];
#pragma unroll
    for (int c = 0; c < NCLS; ++c)
        wt[c] = *reinterpret_cast<const float4*>(&g_wtail[c][cg]);

    float a1x = 0.f, a1y = 0.f, a1z = 0.f, a1w = 0.f;
    float a2x = 0.f, a2y = 0.f, a2z = 0.f, a2w = 0.f;
#pragma unroll
    for (int rr = 0; rr < 2; ++rr) {
        const int row = blockIdx.x * 16 + rr * 8 + rg;
        float4 s = *reinterpret_cast<const float4*>(&g_p1[0][row * 128 + cg]);
        const float4 s1 = *reinterpret_cast<const float4*>(&g_p1[1][row * 128 + cg]);
        const float4 s2 = *reinterpret_cast<const float4*>(&g_p1[2][row * 128 + cg]);
        const float4 s3 = *reinterpret_cast<const float4*>(&g_p1[3][row * 128 + cg]);
        s.x += s1.x + s2.x + s3.x + bv.x;  s.y += s1.y + s2.y + s3.y + bv.y;
        s.z += s1.z + s2.z + s3.z + bv.z;  s.w += s1.w + s2.w + s3.w + bv.w;
#pragma unroll
        for (int c = 0; c < NCLS; ++c) {
            const float lv = lab[row * NCLS + c];
            s.x = fmaf(lv, wt[c].x, s.x); s.y = fmaf(lv, wt[c].y, s.y);
            s.z = fmaf(lv, wt[c].z, s.z); s.w = fmaf(lv, wt[c].w, s.w);
        }
        s.x = leaky(s.x); s.y = leaky(s.y); s.z = leaky(s.z); s.w = leaky(s.w);
        *reinterpret_cast<float4*>(&g_y1[row * 128 + cg]) = s;
        a1x += s.x; a1y += s.y; a1z += s.z; a1w += s.w;
        a2x = fmaf(s.x, s.x, a2x); a2y = fmaf(s.y, s.y, a2y);
        a2z = fmaf(s.z, s.z, a2z); a2w = fmaf(s.w, s.w, a2w);
    }
    sh1[rg][cg + 0] = a1x; sh1[rg][cg + 1] = a1y; sh1[rg][cg + 2] = a1z; sh1[rg][cg + 3] = a1w;
    sh2[rg][cg + 0] = a2x; sh2[rg][cg + 1] = a2y; sh2[rg][cg + 2] = a2z; sh2[rg][cg + 3] = a2w;
    __syncthreads();
    if (tid < 128) {
        float t1 = 0.f, t2 = 0.f;
#pragma unroll
        for (int r = 0; r < 8; ++r) { t1 += sh1[r][tid]; t2 += sh2[r][tid]; }
        g_ps1[blockIdx.x][tid] = t1;
        g_pq1[blockIdx.x][tid] = t2;
    }
}

// =====================================================================
// Launch 5: gemm2 (BN1 finalize fused; BN2 partials emitted)
// =====================================================================
__global__ void __launch_bounds__(256) gemm2_kernel(
    const float* __restrict__ W, const float* __restrict__ bias,
    const float* __restrict__ gamma, const float* __restrict__ beta)
{
    __shared__ float xs[32][32];
    __shared__ float ws[32][128];
    __shared__ float bns[128], bnh[128];
    __shared__ float p1s[8][128];
    __shared__ float p2s[8][128];
    const int rowBase = blockIdx.x * 32;
    const int tid = threadIdx.x;
    const int ty = tid >> 5, tx = tid & 31;

    if (tid < 128) {
        float s1 = 0.f, s2 = 0.f;
#pragma unroll 4
        for (int b = 0; b < 128; ++b) { s1 += g_ps1[b][tid]; s2 += g_pq1[b][tid]; }
        const float mu   = s1 * (1.f / BATCH);
        const float var  = s2 * (1.f / BATCH) - mu * mu;
        const float rstd = rsqrtf(var + 1e-5f);
        const float sc = gamma[tid] * rstd;
        bns[tid] = sc; bnh[tid] = beta[tid] - mu * sc;
    }
    __syncthreads();

    float acc[4][4];
#pragma unroll
    for (int i = 0; i < 4; ++i)
#pragma unroll
        for (int j = 0; j < 4; ++j) acc[i][j] = 0.f;

    for (int kb = 0; kb < 128; kb += 32) {
        __syncthreads();
        {
            const int row = tid & 31;
            const int k4  = (tid >> 5) * 4;
            const float4 vv = *reinterpret_cast<const float4*>(&g_y1[(rowBase + row) * 128 + kb + k4]);
            xs[k4 + 0][row] = fmaf(vv.x, bns[kb + k4 + 0], bnh[kb + k4 + 0]);
            xs[k4 + 1][row] = fmaf(vv.y, bns[kb + k4 + 1], bnh[kb + k4 + 1]);
            xs[k4 + 2][row] = fmaf(vv.z, bns[kb + k4 + 2], bnh[kb + k4 + 2]);
            xs[k4 + 3][row] = fmaf(vv.w, bns[kb + k4 + 3], bnh[kb + k4 + 3]);
        }
        {
            const int col = tid >> 1;
            const int k0  = (tid & 1) * 16;
#pragma unroll
            for (int u = 0; u < 16; u += 4) {
                const float4 vv = *reinterpret_cast<const float4*>(&W[col * 128 + kb + k0 + u]);
                ws[k0 + u + 0][col] = vv.x; ws[k0 + u + 1][col] = vv.y;
                ws[k0 + u + 2][col] = vv.z; ws[k0 + u + 3][col] = vv.w;
            }
        }
        __syncthreads();
#pragma unroll
        for (int kk = 0; kk < 32; ++kk) {
            const float4 A = *reinterpret_cast<const float4*>(&xs[kk][ty * 4]);
            const float4 B = *reinterpret_cast<const float4*>(&ws[kk][tx * 4]);
            const float a[4] = {A.x, A.y, A.z, A.w};
            const float bb[4] = {B.x, B.y, B.z, B.w};
#pragma unroll
            for (int i = 0; i < 4; ++i)
#pragma unroll
                for (int j = 0; j < 4; ++j) acc[i][j] = fmaf(a[i], bb[j], acc[i][j]);
        }
    }
    const float4 bv = *reinterpret_cast<const float4*>(&bias[tx * 4]);
    float c1[4] = {0.f, 0.f, 0.f, 0.f}, c2[4] = {0.f, 0.f, 0.f, 0.f};
#pragma unroll
    for (int i = 0; i < 4; ++i) {
        const int row = rowBase + ty * 4 + i;
        float4 vv = make_float4(leaky(acc[i][0] + bv.x), leaky(acc[i][1] + bv.y),
                                leaky(acc[i][2] + bv.z), leaky(acc[i][3] + bv.w));
        *reinterpret_cast<float4*>(&g_y2[row * 128 + tx * 4]) = vv;
        c1[0] += vv.x; c1[1] += vv.y; c1[2] += vv.z; c1[3] += vv.w;
        c2[0] = fmaf(vv.x, vv.x, c2[0]); c2[1] = fmaf(vv.y, vv.y, c2[1]);
        c2[2] = fmaf(vv.z, vv.z, c2[2]); c2[3] = fmaf(vv.w, vv.w, c2[3]);
    }
#pragma unroll
    for (int j = 0; j < 4; ++j) { p1s[ty][tx * 4 + j] = c1[j]; p2s[ty][tx * 4 + j] = c2[j]; }
    __syncthreads();
    if (tid < 128) {
        float a1 = 0.f, a2 = 0.f;
#pragma unroll
        for (int r = 0; r < 8; ++r) { a1 += p1s[r][tid]; a2 += p2s[r][tid]; }
        g_ps2[blockIdx.x][tid] = a1;
        g_pq2[blockIdx.x][tid] = a2;
    }
}

// =====================================================================
// Launch 6: gemm3 (BN2 finalize fused)
// =====================================================================
__global__ void __launch_bounds__(256) gemm3_kernel(
    const float* __restrict__ W, const float* __restrict__ bias,
    const float* __restrict__ gamma, const float* __restrict__ beta,
    float* __restrict__ out)
{
    __shared__ float xs[32][32];
    __shared__ float ws[32][64];
    __shared__ float bns[128], bnh[128];
    const int rowBase = blockIdx.x * 32;
    const int tid = threadIdx.x;
    const int ty = tid >> 4;
    const int tx = tid & 15;

    if (tid < 128) {
        float s1 = 0.f, s2 = 0.f;
#pragma unroll
        for (int b = 0; b < 64; ++b) { s1 += g_ps2[b][tid]; s2 += g_pq2[b][tid]; }
        const float mu   = s1 * (1.f / BATCH);
        const float var  = s2 * (1.f / BATCH) - mu * mu;
        const float rstd = rsqrtf(var + 1e-5f);
        const float sc = gamma[tid] * rstd;
        bns[tid] = sc; bnh[tid] = beta[tid] - mu * sc;
    }
    __syncthreads();

    float acc[2][4];
#pragma unroll
    for (int i = 0; i < 2; ++i)
#pragma unroll
        for (int j = 0; j < 4; ++j) acc[i][j] = 0.f;

    for (int kb = 0; kb < 128; kb += 32) {
        __syncthreads();
        {
            const int row = tid & 31;
            const int k4  = (tid >> 5) * 4;
            const float4 vv = *reinterpret_cast<const float4*>(&g_y2[(rowBase + row) * 128 + kb + k4]);
            xs[k4 + 0][row] = fmaf(vv.x, bns[kb + k4 + 0], bnh[kb + k4 + 0]);
            xs[k4 + 1][row] = fmaf(vv.y, bns[kb + k4 + 1], bnh[kb + k4 + 1]);
            xs[k4 + 2][row] = fmaf(vv.z, bns[kb + k4 + 2], bnh[kb + k4 + 2]);
            xs[k4 + 3][row] = fmaf(vv.w, bns[kb + k4 + 3], bnh[kb + k4 + 3]);
        }
        {
            const int col = tid >> 2;
            const int k0  = (tid & 3) * 8;
#pragma unroll
            for (int u = 0; u < 8; u += 4) {
                const float4 vv = *reinterpret_cast<const float4*>(&W[col * 128 + kb + k0 + u]);
                ws[k0 + u + 0][col] = vv.x; ws[k0 + u + 1][col] = vv.y;
                ws[k0 + u + 2][col] = vv.z; ws[k0 + u + 3][col] = vv.w;
            }
        }
        __syncthreads();
#pragma unroll
        for (int kk = 0; kk < 32; ++kk) {
            const float2 A = *reinterpret_cast<const float2*>(&xs[kk][ty * 2]);
            const float4 B = *reinterpret_cast<const float4*>(&ws[kk][tx * 4]);
            const float a[2] = {A.x, A.y};
            const float bb[4] = {B.x, B.y, B.z, B.w};
#pragma unroll
            for (int i = 0; i < 2; ++i)
#pragma unroll
                for (int j = 0; j < 4; ++j) acc[i][j] = fmaf(a[i], bb[j], acc[i][j]);
        }
    }
    const float4 bv = *reinterpret_cast<const float4*>(&bias[tx * 4]);
#pragma unroll
    for (int i = 0; i < 2; ++i) {
        const int row = rowBase + ty * 2 + i;
        float4 vv = make_float4(tanhf(acc[i][0] + bv.x), tanhf(acc[i][1] + bv.y),
                                tanhf(acc[i][2] + bv.z), tanhf(acc[i][3] + bv.w));
        *reinterpret_cast<float4*>(&out[row * 64 + tx * 4]) = vv;
    }
}

// =====================================================================
extern "C" void kernel_launch(void* const* d_in, const int* in_sizes, int n_in,
                              void* d_out, int out_size)
{
    const float* noise  = (const float*)d_in[0];
    const float* labels = (const float*)d_in[1];
    const float* qparams= (const float*)d_in[2];
    const float* ew1 = (const float*)d_in[3];  const float* eb1 = (const float*)d_in[4];
    const float* ew2 = (const float*)d_in[5];  const float* eb2 = (const float*)d_in[6];
    const float* ew3 = (const float*)d_in[7];  const float* eb3 = (const float*)d_in[8];
    const float* pw1 = (const float*)d_in[9];  const float* pb1 = (const float*)d_in[10];
    const float* g1  = (const float*)d_in[11]; const float* be1 = (const float*)d_in[12];
    const float* pw2 = (const float*)d_in[13]; const float* pb2 = (const float*)d_in[14];
    const float* g2  = (const float*)d_in[15]; const float* be2 = (const float*)d_in[16];
    const float* pw3 = (const float*)d_in[17]; const float* pb3 = (const float*)d_in[18];
    float* out = (float*)d_out;

    embed_kernel<<<257, 256>>>(labels, qparams, pw1, ew1, eb1, ew2, eb2, ew3, eb3);  // 1
    qsim_kernel<<<BATCH * NGEN / 4, 128>>>(noise);      // 2
    gemm1p_kernel<<<128, 256>>>(pw1);                   // 3
    reduce1_kernel<<<128, 256>>>(labels, pb1);          // 4
    gemm2_kernel<<<64, 256>>>(pw2, pb2, g1, be1);       // 5
    gemm3_kernel<<<64, 256>>>(pw3, pb3, g2, be2, out);  // 6
}